// round 6
// baseline (speedup 1.0000x reference)
#include <cuda_runtime.h>
#include <cuda_bf16.h>
#include <cstdint>

#define BB 64
#define NN 147
#define NSQ (NN*NN)          // 21609

// ---------------- scratch (device globals; no allocation allowed) ------------
__device__ float g_ahat[(size_t)BB * NSQ];      // A_hat (unnormalized) [b][t][s]
__device__ float g_dinv[BB * NN];
__device__ float g_x0[(size_t)BB * NN * 32];    // node features
__device__ uint32_t g_xwA[((size_t)BB * NN + 16) * 128];  // XW (tf32) ping
__device__ uint32_t g_xwB[((size_t)BB * NN + 16) * 128];  // XW (tf32) pong
__device__ float g_fa[(size_t)BB * NN * 128];   // final GCN output (fp32)

#define CST_W 20                     // conv2 weight k-stride (plain order)
#define CST_P 24                     // conv2 patch k-stride (interleaved order)
#define SW_FLTS (9*32*CST_W)         // 5760
#define PATCH_FLTS (180*CST_P)       // 4320 (also hosts sOut 128*33=4224)

__device__ uint32_t g_w2t[SW_FLTS];  // conv2 weights tf32, [tap*32+o]*CST_W+ci
__device__ uint32_t g_w1t[32*16];    // conv1 weights tf32, [k][o], k>=27 -> 0

__device__ __forceinline__ uint32_t f2tf32(float f) {
    uint32_t r;
    asm("cvt.rna.tf32.f32 %0, %1;" : "=r"(r) : "f"(f));
    return r;
}

#define MMA_TF32(d, a0_, a1_, a2_, a3_, b0_, b1_)                              \
    asm volatile("mma.sync.aligned.m16n8k8.row.col.f32.tf32.tf32.f32 "         \
                 "{%0,%1,%2,%3}, {%4,%5,%6,%7}, {%8,%9}, {%0,%1,%2,%3};"       \
                 : "+f"((d)[0]), "+f"((d)[1]), "+f"((d)[2]), "+f"((d)[3])      \
                 : "r"(a0_), "r"(a1_), "r"(a2_), "r"(a3_), "r"(b0_), "r"(b1_))

// ---------------- one-time weight relayout/convert ---------------------------
__global__ void prep_kernel(const float* __restrict__ w1,
                            const float* __restrict__ w2) {
    int i = blockIdx.x * 256 + threadIdx.x;
    if (i < SW_FLTS) {
        int rowr = i / CST_W, ci = i - rowr * CST_W;
        int tap = rowr >> 5, o = rowr & 31;
        g_w2t[i] = (ci < 16) ? f2tf32(w2[(o*16 + ci)*9 + tap]) : 0u;
    }
    if (i < 512) {
        int k = i >> 4, o = i & 15;
        uint32_t v = 0u;
        if (k < 27) {
            int tap = (k*11) >> 5, c = k - 3*tap;
            int kh = (tap*11) >> 5, kw = tap - 3*kh;
            v = f2tf32(w1[((o*3 + c)*3 + kh)*3 + kw]);   // OIHW
        }
        g_w1t[i] = v;
    }
}

// ====== fused conv1(3->16, MMA) + conv2(16->32, MMA) + ew/A_hat/diag =========
// grid: (10, 19, B). block = 128 threads = 8x16 output tile.
__global__ void __launch_bounds__(128)
conv_fused_kernel(const float* __restrict__ obs,
                  const float* __restrict__ b1,
                  const float* __restrict__ b2) {
    __shared__ float s_all[SW_FLTS + PATCH_FLTS];   // 40.3 KB
    __shared__ uint32_t sObs32[800];     // 12x20x3 tf32 patch + zero pad
    __shared__ uint32_t sW1u[512];       // [k=32][o=16]
    __shared__ float sb1[16];
    __shared__ float sb2[32];
    uint32_t* sWu = (uint32_t*)s_all;
    uint32_t* sPu = (uint32_t*)(s_all + SW_FLTS);
    float*    sOut = s_all + SW_FLTS;

    int tid = threadIdx.x;
    int lane = tid & 31, warp = tid >> 5;
    int b   = blockIdx.z;
    int bw0 = blockIdx.x * 16;
    int bh0 = blockIdx.y * 8;

    // stage weights (precomputed tf32): pure coalesced copies
    {
        uint4* dst = (uint4*)sWu;
        const uint4* src = (const uint4*)g_w2t;
        for (int i = tid; i < SW_FLTS/4; i += 128) dst[i] = src[i];
        ((uint4*)sW1u)[tid] = ((const uint4*)g_w1t)[tid];
    }
    if (tid < 16) sb1[tid] = b1[tid];
    if (tid < 32) sb2[tid] = b2[tid];
    if (tid < 80) sObs32[720 + tid] = 0u;    // pad must be finite (pad-k reads)

    // obs halo patch (tf32): rows bh0-2..bh0+9, cols bw0-2..bw0+17, coalesced
    for (int i = tid; i < 720; i += 128) {
        int pr = i / 60, within = i - pr*60;
        int hi = bh0 + pr - 2;
        int wi = bw0 - 2 + within/3;
        float v = 0.0f;
        if (hi >= 0 && hi < NN && wi >= 0 && wi < NN)
            v = obs[(size_t)(b*NN + hi)*NN*3 + (bw0 - 2)*3 + within];
        sObs32[i] = f2tf32(v);
    }
    __syncthreads();

    int row = lane >> 2, kq = lane & 3;

    // ---------- conv1 via MMA: A = 192 pixels x K32 (im2col), B = w1 --------
    {
        int offA[4][2];
#pragma unroll
        for (int ks = 0; ks < 4; ks++) {
#pragma unroll
            for (int hh = 0; hh < 2; hh++) {
                int k = ks*8 + kq + hh*4;
                int tap = (k*11) >> 5, c = k - 3*tap;
                int kh = (tap*11) >> 5, kw = tap - 3*kh;
                offA[ks][hh] = kh*60 + kw*3 + c;
            }
        }

        float accP[3][2][4];
#pragma unroll
        for (int mt = 0; mt < 3; mt++)
#pragma unroll
            for (int nt = 0; nt < 2; nt++)
#pragma unroll
                for (int q = 0; q < 4; q++) accP[mt][nt][q] = 0.0f;

#pragma unroll
        for (int mt = 0; mt < 3; mt++) {
            int p1 = warp*48 + mt*16 + row;
            int p2 = p1 + 8;
            int p1c = min(p1, 179), p2c = min(p2, 179);
            int pr1 = p1c / 18, pr2 = p2c / 18;
            int bp1 = pr1*60 + (p1c - pr1*18)*3;
            int bp2 = pr2*60 + (p2c - pr2*18)*3;
#pragma unroll
            for (int ks = 0; ks < 4; ks++) {
                uint32_t a0 = sObs32[bp1 + offA[ks][0]];
                uint32_t a1 = sObs32[bp2 + offA[ks][0]];
                uint32_t a2 = sObs32[bp1 + offA[ks][1]];
                uint32_t a3 = sObs32[bp2 + offA[ks][1]];
#pragma unroll
                for (int nt = 0; nt < 2; nt++) {
                    int n = nt*8 + row;
                    uint32_t b0 = sW1u[(ks*8 + kq)*16 + n];
                    uint32_t b1v = sW1u[(ks*8 + kq + 4)*16 + n];
                    MMA_TF32(accP[mt][nt], a0, a1, a2, a3, b0, b1v);
                }
            }
        }

        // bias+relu, ZERO out-of-image pixels, tf32 -> sPu interleaved k-order
        int colq = (lane & 3)*2;
#pragma unroll
        for (int mt = 0; mt < 3; mt++) {
            int ps[2] = { warp*48 + mt*16 + row, warp*48 + mt*16 + row + 8 };
#pragma unroll
            for (int hp = 0; hp < 2; hp++) {
                int p = ps[hp];
                if (p < 180) {
                    int pr = p / 18, pc = p - pr*18;
                    int hi = bh0 + pr - 1, wi = bw0 + pc - 1;
                    bool valid = (hi >= 0 && hi < NN && wi >= 0 && wi < NN);
#pragma unroll
                    for (int nt = 0; nt < 2; nt++) {
                        int ch = nt*8 + colq;
                        float v0 = 0.0f, v1 = 0.0f;
                        if (valid) {
                            v0 = fmaxf(accP[mt][nt][hp*2]   + sb1[ch],   0.0f);
                            v1 = fmaxf(accP[mt][nt][hp*2+1] + sb1[ch+1], 0.0f);
                        }
                        int kb = ch & 8, c0 = ch & 7;
                        int dest0 = ((c0 & 3) << 1) | (c0 >> 2);
                        sPu[p*CST_P + kb + dest0]     = f2tf32(v0);
                        sPu[p*CST_P + kb + dest0 + 2] = f2tf32(v1);
                    }
                }
            }
        }
    }
    __syncthreads();

    // ---------- conv2 via MMA: K = 9 taps x 16 ci, M = 128 px, N = 32 -------
    float acc[2][4][4];
#pragma unroll
    for (int mt = 0; mt < 2; mt++)
#pragma unroll
        for (int nt = 0; nt < 4; nt++)
#pragma unroll
            for (int q = 0; q < 4; q++) acc[mt][nt][q] = 0.0f;

    int pw0 = row, kk = kq, og = row;

#pragma unroll
    for (int th = 0; th < 3; th++) {
#pragma unroll
        for (int tw = 0; tw < 3; tw++) {
            int tap = th*3 + tw;
#pragma unroll
            for (int ks = 0; ks < 2; ks++) {
                int kb = ks * 8;
                uint32_t bf[4][2];
#pragma unroll
                for (int nt = 0; nt < 4; nt++) {
                    int o = nt*8 + og;
                    bf[nt][0] = sWu[(tap*32 + o)*CST_W + kb + kk];
                    bf[nt][1] = sWu[(tap*32 + o)*CST_W + kb + kk + 4];
                }
#pragma unroll
                for (int mt = 0; mt < 2; mt++) {
                    int ph = warp*2 + mt;
                    int base = ((ph + th)*18 + tw + pw0)*CST_P + kb + 2*kk;
                    uint2 A0 = *(const uint2*)&sPu[base];
                    uint2 A1 = *(const uint2*)&sPu[base + 8*CST_P];
#pragma unroll
                    for (int nt = 0; nt < 4; nt++)
                        MMA_TF32(acc[mt][nt], A0.x, A1.x, A0.y, A1.y,
                                 bf[nt][0], bf[nt][1]);
                }
            }
        }
    }

    __syncthreads();   // patch reads done; reuse buffer as sOut

    int m0 = warp * 32;
#pragma unroll
    for (int mt = 0; mt < 2; mt++) {
        int row0 = m0 + mt*16 + row;
#pragma unroll
        for (int nt = 0; nt < 4; nt++) {
            int col = nt*8 + (lane & 3)*2;
            sOut[row0*33 + col]       = fmaxf(acc[mt][nt][0] + sb2[col],   0.0f);
            sOut[row0*33 + col + 1]   = fmaxf(acc[mt][nt][1] + sb2[col+1], 0.0f);
            sOut[(row0+8)*33 + col]   = fmaxf(acc[mt][nt][2] + sb2[col],   0.0f);
            sOut[(row0+8)*33 + col+1] = fmaxf(acc[mt][nt][3] + sb2[col+1], 0.0f);
        }
    }
    __syncthreads();

    {
        int ph = tid >> 4, pw = tid & 15;
        int h = bh0 + ph, wq = bw0 + pw;
        if (h < NN && wq < NN) {
            float s = 0.0f;
#pragma unroll
            for (int o = 0; o < 32; o++) s += sOut[tid*33 + o];
            float ew = s * (1.0f / 32.0f);
            g_ahat[(size_t)b*NSQ + (size_t)wq*NN + h] = ew + (h == wq ? 1.0f : 0.0f);
            if (h == wq) {
                float* xp = g_x0 + ((size_t)b*NN + h)*32;
#pragma unroll
                for (int o = 0; o < 32; o++) xp[o] = sOut[tid*33 + o];
            }
        }
    }
}

// ---------------- degree / D^-1/2 --------------------------------------------
__global__ void deg_kernel() {
    int bt = blockIdx.x;
    const float* row = g_ahat + (size_t)bt * NN;
    int tid = threadIdx.x;
    float s = 0.0f;
    for (int i = tid; i < NN; i += 128) s += row[i];
#pragma unroll
    for (int o = 16; o > 0; o >>= 1) s += __shfl_xor_sync(0xffffffff, s, o);
    __shared__ float ws[4];
    if ((tid & 31) == 0) ws[tid >> 5] = s;
    __syncthreads();
    if (tid == 0) {
        float d = ws[0] + ws[1] + ws[2] + ws[3];
        g_dinv[bt] = d > 0.0f ? rsqrtf(d) : 0.0f;
    }
}

// ------------- XW1 = x0 @ W1 via tf32 MMA -> tf32 output ---------------------
__global__ void xw1_kernel(const float* __restrict__ X,
                           const float* __restrict__ W,
                           uint32_t* __restrict__ XW) {
    constexpr int FIN = 32, FOUT = 64, NT = FOUT / 8;
    int lane = threadIdx.x & 31, warp = threadIdx.x >> 5;
    int m0 = blockIdx.x * 64 + warp * 16;
    int row = lane >> 2, kq = lane & 3;

    float acc[NT][4];
#pragma unroll
    for (int nt = 0; nt < NT; nt++)
#pragma unroll
        for (int q = 0; q < 4; q++) acc[nt][q] = 0.0f;

    const float* xr0 = X + (size_t)(m0 + row) * FIN;
    const float* xr1 = X + (size_t)(m0 + row + 8) * FIN;

#pragma unroll
    for (int ks = 0; ks < FIN/8; ks++) {
        int k0 = ks*8;
        uint32_t a0 = f2tf32(__ldg(xr0 + k0 + kq));
        uint32_t a1 = f2tf32(__ldg(xr1 + k0 + kq));
        uint32_t a2 = f2tf32(__ldg(xr0 + k0 + kq + 4));
        uint32_t a3 = f2tf32(__ldg(xr1 + k0 + kq + 4));
#pragma unroll
        for (int nt = 0; nt < NT; nt++) {
            int n = nt*8 + row;
            uint32_t b0 = f2tf32(__ldg(W + (size_t)(k0 + kq)*FOUT + n));
            uint32_t b1 = f2tf32(__ldg(W + (size_t)(k0 + kq + 4)*FOUT + n));
            MMA_TF32(acc[nt], a0, a1, a2, a3, b0, b1);
        }
    }

#pragma unroll
    for (int nt = 0; nt < NT; nt++) {
        int col = nt*8 + (lane & 3)*2;
        uint2 v0 = make_uint2(f2tf32(acc[nt][0]), f2tf32(acc[nt][1]));
        uint2 v1 = make_uint2(f2tf32(acc[nt][2]), f2tf32(acc[nt][3]));
        *(uint2*)&XW[(size_t)(m0 + row)     * FOUT + col] = v0;
        *(uint2*)&XW[(size_t)(m0 + row + 8) * FOUT + col] = v1;
    }
}

// --- GCN layer: Y = relu(norm @ XW_in + b); XW_out = Y @ Wn (or Y out) -------
#define AST 156
template<int FOUT, bool LAST>
__global__ void __launch_bounds__(128)
gcn_kernel(const uint32_t* __restrict__ XW_in,
           const float* __restrict__ bias,
           const float* __restrict__ Wn,
           uint32_t* __restrict__ XW_out,
           float* __restrict__ Yout) {
    constexpr int NTW = FOUT / 32;
    constexpr int SYST = FOUT + 4;
    constexpr int FOUT2 = 128;
    __shared__ uint32_t sA[16 * AST];
    __shared__ float sds[160];
    __shared__ uint32_t sY[16 * SYST];

    int tid = threadIdx.x;
    int lane = tid & 31, warp = tid >> 5;
    int b = blockIdx.y, t0 = blockIdx.x * 16;
    int row = lane >> 2, kq = lane & 3;

    for (int i = tid; i < 160; i += 128)
        sds[i] = (i < NN) ? g_dinv[b*NN + i] : 0.0f;
    __syncthreads();

    const float* ab = g_ahat + (size_t)b * NSQ;
    for (int i = tid; i < 16*AST; i += 128) {
        int r = i / AST, s = i - r*AST;
        int t = t0 + r;
        float v = 0.0f;
        if (t < NN && s < NN) v = ab[(size_t)t*NN + s] * sds[t] * sds[s];
        sA[i] = f2tf32(v);
    }
    __syncthreads();

    float acc[NTW][4];
#pragma unroll
    for (int nt = 0; nt < NTW; nt++)
#pragma unroll
        for (int q = 0; q < 4; q++) acc[nt][q] = 0.0f;

    int wn0 = warp * (FOUT/4);
    const uint32_t* xwb = XW_in + (size_t)b * NN * FOUT;

#pragma unroll
    for (int ks = 0; ks < 19; ks++) {
        int k0 = ks*8;
        uint32_t a0 = sA[row*AST + k0 + kq];
        uint32_t a1 = sA[(row+8)*AST + k0 + kq];
        uint32_t a2 = sA[row*AST + k0 + kq + 4];
        uint32_t a3 = sA[(row+8)*AST + k0 + kq + 4];
#pragma unroll
        for (int nt = 0; nt < NTW; nt++) {
            int n = wn0 + nt*8 + row;
            uint32_t b0 = xwb[(size_t)(k0 + kq)*FOUT + n];
            uint32_t b1 = xwb[(size_t)(k0 + kq + 4)*FOUT + n];
            MMA_TF32(acc[nt], a0, a1, a2, a3, b0, b1);
        }
    }

    int r0 = t0 + row, r1 = r0 + 8;
#pragma unroll
    for (int nt = 0; nt < NTW; nt++) {
        int col = wn0 + nt*8 + (lane & 3)*2;
        float bv0 = __ldg(bias + col), bv1 = __ldg(bias + col + 1);
        float y00 = fmaxf(acc[nt][0] + bv0, 0.0f);
        float y01 = fmaxf(acc[nt][1] + bv1, 0.0f);
        float y10 = fmaxf(acc[nt][2] + bv0, 0.0f);
        float y11 = fmaxf(acc[nt][3] + bv1, 0.0f);
        if (LAST) {
            if (r0 < NN)
                *(float2*)&Yout[(size_t)(b*NN + r0)*FOUT + col] = make_float2(y00, y01);
            if (r1 < NN)
                *(float2*)&Yout[(size_t)(b*NN + r1)*FOUT + col] = make_float2(y10, y11);
        } else {
            *(uint2*)&sY[row*SYST + col]     = make_uint2(f2tf32(y00), f2tf32(y01));
            *(uint2*)&sY[(row+8)*SYST + col] = make_uint2(f2tf32(y10), f2tf32(y11));
        }
    }

    if (!LAST) {
        __syncthreads();

        float acc2[4][4];
#pragma unroll
        for (int nt = 0; nt < 4; nt++)
#pragma unroll
            for (int q = 0; q < 4; q++) acc2[nt][q] = 0.0f;

        int wn2 = warp * 32;
#pragma unroll
        for (int ks = 0; ks < FOUT/8; ks++) {
            int k0 = ks*8;
            uint32_t a0 = sY[row*SYST + k0 + kq];
            uint32_t a1 = sY[(row+8)*SYST + k0 + kq];
            uint32_t a2 = sY[row*SYST + k0 + kq + 4];
            uint32_t a3 = sY[(row+8)*SYST + k0 + kq + 4];
#pragma unroll
            for (int nt = 0; nt < 4; nt++) {
                int n = wn2 + nt*8 + row;
                uint32_t b0 = f2tf32(__ldg(Wn + (size_t)(k0 + kq)*FOUT2 + n));
                uint32_t b1 = f2tf32(__ldg(Wn + (size_t)(k0 + kq + 4)*FOUT2 + n));
                MMA_TF32(acc2[nt], a0, a1, a2, a3, b0, b1);
            }
        }

#pragma unroll
        for (int nt = 0; nt < 4; nt++) {
            int col = wn2 + nt*8 + (lane & 3)*2;
            if (r0 < NN) {
                uint2 v = make_uint2(f2tf32(acc2[nt][0]), f2tf32(acc2[nt][1]));
                *(uint2*)&XW_out[(size_t)(b*NN + r0)*FOUT2 + col] = v;
            }
            if (r1 < NN) {
                uint2 v = make_uint2(f2tf32(acc2[nt][2]), f2tf32(acc2[nt][3]));
                *(uint2*)&XW_out[(size_t)(b*NN + r1)*FOUT2 + col] = v;
            }
        }
    }
}

// ---------------- mean pool + policy head ------------------------------------
__global__ void head_kernel(const float* __restrict__ Y,
                            const float* __restrict__ pw,
                            const float* __restrict__ pb,
                            float* __restrict__ out) {
    int b = blockIdx.x;
    __shared__ float sp[128];
    int f = threadIdx.x;
    float s = 0.0f;
    const float* yb = Y + (size_t)b*NN*128;
    for (int n = 0; n < NN; n++) s += yb[n*128 + f];
    sp[f] = s * (1.0f / NN);
    __syncthreads();
    if (f < 5) {
        float a = pb[f];
#pragma unroll
        for (int i = 0; i < 128; i++) a += sp[i] * pw[i*5 + f];
        out[b*5 + f] = a;
    }
}

// ---------------- launch -----------------------------------------------------
extern "C" void kernel_launch(void* const* d_in, const int* in_sizes, int n_in,
                              void* d_out, int out_size) {
    const float* obs      = (const float*)d_in[0];
    const float* conv1_w  = (const float*)d_in[1];
    const float* conv1_b  = (const float*)d_in[2];
    const float* conv2_w  = (const float*)d_in[3];
    const float* conv2_b  = (const float*)d_in[4];
    const float* gcn1_w   = (const float*)d_in[5];
    const float* gcn1_b   = (const float*)d_in[6];
    const float* gcn2_w   = (const float*)d_in[7];
    const float* gcn2_b   = (const float*)d_in[8];
    const float* gcn3_w   = (const float*)d_in[9];
    const float* gcn3_b   = (const float*)d_in[10];
    const float* policy_w = (const float*)d_in[11];
    const float* policy_b = (const float*)d_in[12];
    float* out = (float*)d_out;

    float *x0, *fa;
    uint32_t *xwA, *xwB;
    cudaGetSymbolAddress((void**)&x0, g_x0);
    cudaGetSymbolAddress((void**)&fa, g_fa);
    cudaGetSymbolAddress((void**)&xwA, g_xwA);
    cudaGetSymbolAddress((void**)&xwB, g_xwB);

    prep_kernel<<<23, 256>>>(conv1_w, conv2_w);
    conv_fused_kernel<<<dim3(10, 19, BB), 128>>>(obs, conv1_b, conv2_b);
    deg_kernel<<<BB*NN, 128>>>();

    xw1_kernel<<<147, 128>>>(x0, gcn1_w, xwA);
    gcn_kernel<64,  false><<<dim3(10, BB), 128>>>(xwA, gcn1_b, gcn2_w, xwB, nullptr);
    gcn_kernel<128, false><<<dim3(10, BB), 128>>>(xwB, gcn2_b, gcn3_w, xwA, nullptr);
    gcn_kernel<128, true ><<<dim3(10, BB), 128>>>(xwA, gcn3_b, nullptr, nullptr, fa);

    head_kernel<<<BB, 128>>>(fa, policy_w, policy_b, out);
}

// round 7
// speedup vs baseline: 1.3568x; 1.3568x over previous
#include <cuda_runtime.h>
#include <cuda_fp16.h>
#include <cstdint>

#define BB 64
#define NN 147
#define NSQ (NN*NN)          // 21609

// ---------------- scratch (device globals; zero-initialized) -----------------
__device__ float g_ahat[(size_t)BB * NSQ];      // A_hat (unnormalized) [b][t][s]
__device__ float g_dinv[BB * NN];
__device__ uint32_t g_x0h[(size_t)BB * NN * 16];     // node feats fp16 [node][16 words]
__device__ uint32_t g_xwTA[(size_t)BB * 128 * 80];   // XW^T fp16 [b][f][160 s] ping
__device__ uint32_t g_xwTB[(size_t)BB * 128 * 80];   // pong (pads stay zero)
__device__ float g_fa[(size_t)BB * NN * 128];   // final GCN output (fp32)

__device__ uint32_t g_w2h[9*32*12];  // conv2 w fp16: [(tap*32+o)*12 + q], q=ci/2
__device__ uint32_t g_w1t[32*16];    // conv1 w tf32: [k][o], k>=27 -> 0
__device__ uint32_t g_wg1[64*16];    // gcn1_w fp16 T: [n][q=k/2], K=32
__device__ uint32_t g_wg2[128*32];   // gcn2_w fp16 T: [n][q], K=64
__device__ uint32_t g_wg3[128*64];   // gcn3_w fp16 T: [n][q], K=128

__device__ __forceinline__ uint32_t f2tf32(float f) {
    uint32_t r;
    asm("cvt.rna.tf32.f32 %0, %1;" : "=r"(r) : "f"(f));
    return r;
}
__device__ __forceinline__ uint32_t packh2(float lo, float hi) {
    __half2 h = __floats2half2_rn(lo, hi);
    return *(uint32_t*)&h;
}

#define MMA_TF32(d, a0_, a1_, a2_, a3_, b0_, b1_)                              \
    asm volatile("mma.sync.aligned.m16n8k8.row.col.f32.tf32.tf32.f32 "         \
                 "{%0,%1,%2,%3}, {%4,%5,%6,%7}, {%8,%9}, {%0,%1,%2,%3};"       \
                 : "+f"((d)[0]), "+f"((d)[1]), "+f"((d)[2]), "+f"((d)[3])      \
                 : "r"(a0_), "r"(a1_), "r"(a2_), "r"(a3_), "r"(b0_), "r"(b1_))

#define MMA_F16(d, a0_, a1_, a2_, a3_, b0_, b1_)                               \
    asm volatile("mma.sync.aligned.m16n8k16.row.col.f32.f16.f16.f32 "          \
                 "{%0,%1,%2,%3}, {%4,%5,%6,%7}, {%8,%9}, {%0,%1,%2,%3};"       \
                 : "+f"((d)[0]), "+f"((d)[1]), "+f"((d)[2]), "+f"((d)[3])      \
                 : "r"(a0_), "r"(a1_), "r"(a2_), "r"(a3_), "r"(b0_), "r"(b1_))

// ---------------- one-time weight relayout/convert ---------------------------
__global__ void prep_a(const float* __restrict__ w1, const float* __restrict__ w2) {
    int i = blockIdx.x * 256 + threadIdx.x;
    if (i < 2304) {                      // conv2 -> fp16 pairs
        int tap = i >> 8, rem = i & 255, o = rem >> 3, q = rem & 7;
        g_w2h[(tap*32 + o)*12 + q] =
            packh2(w2[(o*16 + 2*q)*9 + tap], w2[(o*16 + 2*q + 1)*9 + tap]);
    }
    if (i < 512) {                       // conv1 -> tf32, k>=27 zero
        int k = i >> 4, o = i & 15;
        uint32_t v = 0u;
        if (k < 27) {
            int tap = (k*11) >> 5, c = k - 3*tap;
            int kh = (tap*11) >> 5, kw = tap - 3*kh;
            v = f2tf32(w1[((o*3 + c)*3 + kh)*3 + kw]);   // OIHW
        }
        g_w1t[i] = v;
    }
}
__global__ void prep_b(const float* __restrict__ wg1, const float* __restrict__ wg3) {
    int i = blockIdx.x * 256 + threadIdx.x;
    if (i < 1024) {
        int n = i >> 4, q = i & 15;
        g_wg1[i] = packh2(wg1[2*q*64 + n], wg1[(2*q + 1)*64 + n]);
    }
    if (i < 8192) {
        int n = i >> 6, q = i & 63;
        g_wg3[i] = packh2(wg3[2*q*128 + n], wg3[(2*q + 1)*128 + n]);
    }
}
__global__ void prep_c(const float* __restrict__ wg2) {
    int i = blockIdx.x * 256 + threadIdx.x;
    if (i < 4096) {
        int n = i >> 5, q = i & 31;
        g_wg2[i] = packh2(wg2[2*q*128 + n], wg2[(2*q + 1)*128 + n]);
    }
}

// ====== fused conv1(3->16, tf32 MMA) + conv2(16->32, fp16 MMA) + epilogue ====
// grid: (10, 19, B). block = 128 threads = 8x16 output tile.
#define PST 12                            // patch pixel stride (words, half2)
__global__ void __launch_bounds__(128)
conv_fused_kernel(const float* __restrict__ obs,
                  const float* __restrict__ b1,
                  const float* __restrict__ b2) {
    __shared__ uint32_t sW2h[9*32*12];    // 13.8 KB
    __shared__ float sRegion[4224];       // patch (2160 w) then sOut (4224 w)
    __shared__ uint32_t sObs32[800];
    __shared__ uint32_t sW1u[512];
    __shared__ float sb1[16];
    __shared__ float sb2[32];
    uint32_t* sPu = (uint32_t*)sRegion;
    float*    sOut = sRegion;

    int tid = threadIdx.x;
    int lane = tid & 31, warp = tid >> 5;
    int gid = lane >> 2, tig = lane & 3;
    int b   = blockIdx.z;
    int bw0 = blockIdx.x * 16;
    int bh0 = blockIdx.y * 8;

    {   // stage weights: coalesced copies
        uint4* dst = (uint4*)sW2h;
        const uint4* src = (const uint4*)g_w2h;
        for (int i = tid; i < 9*32*12/4; i += 128) dst[i] = src[i];
        ((uint4*)sW1u)[tid] = ((const uint4*)g_w1t)[tid];
    }
    if (tid < 16) sb1[tid] = b1[tid];
    if (tid < 32) sb2[tid] = b2[tid];
    if (tid < 80) sObs32[720 + tid] = 0u;

    // obs halo patch (tf32): rows bh0-2..bh0+9, cols bw0-2..bw0+17
    for (int i = tid; i < 720; i += 128) {
        int pr = i / 60, within = i - pr*60;
        int hi = bh0 + pr - 2;
        int wi = bw0 - 2 + within/3;
        float v = 0.0f;
        if (hi >= 0 && hi < NN && wi >= 0 && wi < NN)
            v = obs[(size_t)(b*NN + hi)*NN*3 + (bw0 - 2)*3 + within];
        sObs32[i] = f2tf32(v);
    }
    __syncthreads();

    // ---------- conv1 via tf32 MMA: A = 192 px x K32 im2col, B = w1 ---------
    {
        int offA[4][2];
#pragma unroll
        for (int ks = 0; ks < 4; ks++) {
#pragma unroll
            for (int hh = 0; hh < 2; hh++) {
                int k = ks*8 + tig + hh*4;
                int tap = (k*11) >> 5, c = k - 3*tap;
                int kh = (tap*11) >> 5, kw = tap - 3*kh;
                offA[ks][hh] = kh*60 + kw*3 + c;
            }
        }

        float accP[3][2][4];
#pragma unroll
        for (int mt = 0; mt < 3; mt++)
#pragma unroll
            for (int nt = 0; nt < 2; nt++)
#pragma unroll
                for (int q = 0; q < 4; q++) accP[mt][nt][q] = 0.0f;

#pragma unroll
        for (int mt = 0; mt < 3; mt++) {
            int p1 = warp*48 + mt*16 + gid;
            int p2 = p1 + 8;
            int p1c = min(p1, 179), p2c = min(p2, 179);
            int pr1 = p1c / 18, pr2 = p2c / 18;
            int bp1 = pr1*60 + (p1c - pr1*18)*3;
            int bp2 = pr2*60 + (p2c - pr2*18)*3;
#pragma unroll
            for (int ks = 0; ks < 4; ks++) {
                uint32_t a0 = sObs32[bp1 + offA[ks][0]];
                uint32_t a1 = sObs32[bp2 + offA[ks][0]];
                uint32_t a2 = sObs32[bp1 + offA[ks][1]];
                uint32_t a3 = sObs32[bp2 + offA[ks][1]];
#pragma unroll
                for (int nt = 0; nt < 2; nt++) {
                    int n = nt*8 + gid;
                    uint32_t b0 = sW1u[(ks*8 + tig)*16 + n];
                    uint32_t b1v = sW1u[(ks*8 + tig + 4)*16 + n];
                    MMA_TF32(accP[mt][nt], a0, a1, a2, a3, b0, b1v);
                }
            }
        }

        // bias+relu, zero invalid pixels, pack fp16 pairs -> sPu[p*PST + ch/2]
#pragma unroll
        for (int mt = 0; mt < 3; mt++) {
            int ps[2] = { warp*48 + mt*16 + gid, warp*48 + mt*16 + gid + 8 };
#pragma unroll
            for (int hp = 0; hp < 2; hp++) {
                int p = ps[hp];
                if (p < 180) {
                    int pr = p / 18, pc = p - pr*18;
                    int hi = bh0 + pr - 1, wi = bw0 + pc - 1;
                    bool valid = (hi >= 0 && hi < NN && wi >= 0 && wi < NN);
#pragma unroll
                    for (int nt = 0; nt < 2; nt++) {
                        int ch = nt*8 + 2*tig;
                        float v0 = 0.0f, v1 = 0.0f;
                        if (valid) {
                            v0 = fmaxf(accP[mt][nt][hp*2]   + sb1[ch],   0.0f);
                            v1 = fmaxf(accP[mt][nt][hp*2+1] + sb1[ch+1], 0.0f);
                        }
                        sPu[p*PST + nt*4 + tig] = packh2(v0, v1);
                    }
                }
            }
        }
    }
    __syncthreads();

    // ---------- conv2 via fp16 MMA: one k16 chunk per tap --------------------
    float acc[2][4][4];
#pragma unroll
    for (int mt = 0; mt < 2; mt++)
#pragma unroll
        for (int nt = 0; nt < 4; nt++)
#pragma unroll
            for (int q = 0; q < 4; q++) acc[mt][nt][q] = 0.0f;

#pragma unroll
    for (int th = 0; th < 3; th++) {
#pragma unroll
        for (int tw = 0; tw < 3; tw++) {
            int tap = th*3 + tw;
            uint32_t bf[4][2];
#pragma unroll
            for (int nt = 0; nt < 4; nt++) {
                int o = nt*8 + gid;
                bf[nt][0] = sW2h[(tap*32 + o)*12 + tig];
                bf[nt][1] = sW2h[(tap*32 + o)*12 + tig + 4];
            }
#pragma unroll
            for (int mt = 0; mt < 2; mt++) {
                int ph = warp*2 + mt;
                int P1 = (ph + th)*18 + gid + tw;
                uint32_t a0 = sPu[P1*PST + tig];
                uint32_t a1 = sPu[(P1+8)*PST + tig];
                uint32_t a2 = sPu[P1*PST + tig + 4];
                uint32_t a3 = sPu[(P1+8)*PST + tig + 4];
#pragma unroll
                for (int nt = 0; nt < 4; nt++)
                    MMA_F16(acc[mt][nt], a0, a1, a2, a3, bf[nt][0], bf[nt][1]);
            }
        }
    }

    __syncthreads();   // patch reads done; reuse buffer as sOut

    int m0 = warp * 32;
#pragma unroll
    for (int mt = 0; mt < 2; mt++) {
        int row0 = m0 + mt*16 + gid;
#pragma unroll
        for (int nt = 0; nt < 4; nt++) {
            int col = nt*8 + 2*tig;
            sOut[row0*33 + col]       = fmaxf(acc[mt][nt][0] + sb2[col],   0.0f);
            sOut[row0*33 + col + 1]   = fmaxf(acc[mt][nt][1] + sb2[col+1], 0.0f);
            sOut[(row0+8)*33 + col]   = fmaxf(acc[mt][nt][2] + sb2[col],   0.0f);
            sOut[(row0+8)*33 + col+1] = fmaxf(acc[mt][nt][3] + sb2[col+1], 0.0f);
        }
    }
    __syncthreads();

    {   // per-pixel: channel mean -> A_hat (transposed, +I); diag -> x0 (fp16)
        int ph = tid >> 4, pw = tid & 15;
        int h = bh0 + ph, wq = bw0 + pw;
        if (h < NN && wq < NN) {
            float s = 0.0f;
#pragma unroll
            for (int o = 0; o < 32; o++) s += sOut[tid*33 + o];
            float ew = s * (1.0f / 32.0f);
            g_ahat[(size_t)b*NSQ + (size_t)wq*NN + h] = ew + (h == wq ? 1.0f : 0.0f);
            if (h == wq) {
                uint32_t* xp = g_x0h + ((size_t)b*NN + h)*16;
#pragma unroll
                for (int o = 0; o < 16; o++)
                    xp[o] = packh2(sOut[tid*33 + 2*o], sOut[tid*33 + 2*o + 1]);
            }
        }
    }
}

// ---------------- degree / D^-1/2 --------------------------------------------
__global__ void deg_kernel() {
    int bt = blockIdx.x;
    const float* row = g_ahat + (size_t)bt * NN;
    int tid = threadIdx.x;
    float s = 0.0f;
    for (int i = tid; i < NN; i += 128) s += row[i];
#pragma unroll
    for (int o = 16; o > 0; o >>= 1) s += __shfl_xor_sync(0xffffffff, s, o);
    __shared__ float ws[4];
    if ((tid & 31) == 0) ws[tid >> 5] = s;
    __syncthreads();
    if (tid == 0) {
        float d = ws[0] + ws[1] + ws[2] + ws[3];
        g_dinv[bt] = d > 0.0f ? rsqrtf(d) : 0.0f;
    }
}

// -------- XW1^T = (x0 @ W1)^T via fp16 MMA; out fp16 [b][f][160] -------------
__global__ void xw1_kernel() {
    int lane = threadIdx.x & 31, warp = threadIdx.x >> 5;
    int gid = lane >> 2, tig = lane & 3;
    int m0 = blockIdx.x * 64 + warp * 16;

    float acc[8][4];
#pragma unroll
    for (int nt = 0; nt < 8; nt++)
#pragma unroll
        for (int q = 0; q < 4; q++) acc[nt][q] = 0.0f;

    int r0 = m0 + gid, r1 = r0 + 8;
#pragma unroll
    for (int ks = 0; ks < 2; ks++) {
        uint32_t a0 = g_x0h[(size_t)r0*16 + ks*8 + tig];
        uint32_t a1 = g_x0h[(size_t)r1*16 + ks*8 + tig];
        uint32_t a2 = g_x0h[(size_t)r0*16 + ks*8 + tig + 4];
        uint32_t a3 = g_x0h[(size_t)r1*16 + ks*8 + tig + 4];
#pragma unroll
        for (int nt = 0; nt < 8; nt++) {
            int n = nt*8 + gid;
            uint32_t b0 = g_wg1[n*16 + ks*8 + tig];
            uint32_t b1 = g_wg1[n*16 + ks*8 + tig + 4];
            MMA_F16(acc[nt], a0, a1, a2, a3, b0, b1);
        }
    }

    __half* dst = (__half*)g_xwTA;
    int b0i = r0 / NN, s0 = r0 - b0i*NN;
    int b1i = r1 / NN, s1 = r1 - b1i*NN;
#pragma unroll
    for (int nt = 0; nt < 8; nt++) {
        int col = nt*8 + 2*tig;
        dst[((size_t)b0i*128 + col    )*160 + s0] = __float2half(acc[nt][0]);
        dst[((size_t)b0i*128 + col + 1)*160 + s0] = __float2half(acc[nt][1]);
        dst[((size_t)b1i*128 + col    )*160 + s1] = __float2half(acc[nt][2]);
        dst[((size_t)b1i*128 + col + 1)*160 + s1] = __float2half(acc[nt][3]);
    }
}

// --- GCN layer: Y = relu(norm @ XW_in^T' + b); then XW_out^T = (Y @ Wn)^T ----
template<int FOUT, bool LAST>
__global__ void __launch_bounds__(128)
gcn_kernel(const uint32_t* __restrict__ XWT_in,
           const float* __restrict__ bias,
           const uint32_t* __restrict__ Wn,
           uint32_t* __restrict__ XWT_out,
           float* __restrict__ Yout) {
    constexpr int NTW  = FOUT / 32;       // n8-tiles per warp, 1st gemm
    constexpr int SYW  = FOUT/2 + 4;      // sY row stride in words
    __shared__ uint32_t sA[16 * 84];      // fp16 norm tile, stride 84 words
    __shared__ float sds[160];
    __shared__ uint32_t sY[16 * SYW];

    int tid = threadIdx.x;
    int lane = tid & 31, warp = tid >> 5;
    int gid = lane >> 2, tig = lane & 3;
    int b = blockIdx.y, t0 = blockIdx.x * 16;

    for (int i = tid; i < 160; i += 128)
        sds[i] = (i < NN) ? g_dinv[b*NN + i] : 0.0f;
    __syncthreads();

    {   // stage normalized A tile as fp16, zero-padded to 168 halves/row
        __half* sAh = (__half*)sA;
        const float* ab = g_ahat + (size_t)b * NSQ;
        for (int i = tid; i < 16*168; i += 128) {
            int r = i / 168, s = i - r*168;
            int t = t0 + r;
            float v = 0.0f;
            if (t < NN && s < NN) v = ab[(size_t)t*NN + s] * sds[t] * sds[s];
            sAh[r*168 + s] = __float2half(v);
        }
    }
    __syncthreads();

    float acc[NTW][4];
#pragma unroll
    for (int nt = 0; nt < NTW; nt++)
#pragma unroll
        for (int q = 0; q < 4; q++) acc[nt][q] = 0.0f;

    int wn0 = warp * (FOUT/4);
    const uint32_t* xwb = XWT_in + (size_t)b * 128 * 80;

#pragma unroll
    for (int ks = 0; ks < 10; ks++) {      // K = 160 (s-padded, pads are zero)
        uint32_t a0 = sA[gid*84 + ks*8 + tig];
        uint32_t a1 = sA[(gid+8)*84 + ks*8 + tig];
        uint32_t a2 = sA[gid*84 + ks*8 + tig + 4];
        uint32_t a3 = sA[(gid+8)*84 + ks*8 + tig + 4];
#pragma unroll
        for (int nt = 0; nt < NTW; nt++) {
            int n = wn0 + nt*8 + gid;
            uint32_t b0 = __ldg(xwb + (size_t)n*80 + ks*8 + tig);
            uint32_t b1 = __ldg(xwb + (size_t)n*80 + ks*8 + tig + 4);
            MMA_F16(acc[nt], a0, a1, a2, a3, b0, b1);
        }
    }

    int r0 = t0 + gid, r1 = r0 + 8;
#pragma unroll
    for (int nt = 0; nt < NTW; nt++) {
        int col = wn0 + nt*8 + 2*tig;
        float bv0 = __ldg(bias + col), bv1 = __ldg(bias + col + 1);
        float y00 = fmaxf(acc[nt][0] + bv0, 0.0f);
        float y01 = fmaxf(acc[nt][1] + bv1, 0.0f);
        float y10 = fmaxf(acc[nt][2] + bv0, 0.0f);
        float y11 = fmaxf(acc[nt][3] + bv1, 0.0f);
        if (LAST) {
            if (r0 < NN)
                *(float2*)&Yout[(size_t)(b*NN + r0)*FOUT + col] = make_float2(y00, y01);
            if (r1 < NN)
                *(float2*)&Yout[(size_t)(b*NN + r1)*FOUT + col] = make_float2(y10, y11);
        } else {
            int wq = wn0/2 + nt*4 + tig;
            sY[gid*SYW + wq]     = packh2(y00, y01);
            sY[(gid+8)*SYW + wq] = packh2(y10, y11);
        }
    }

    if (!LAST) {
        __syncthreads();

        float acc2[4][4];
#pragma unroll
        for (int nt = 0; nt < 4; nt++)
#pragma unroll
            for (int q = 0; q < 4; q++) acc2[nt][q] = 0.0f;

        int wn2 = warp * 32;
#pragma unroll
        for (int ks = 0; ks < FOUT/16; ks++) {
            uint32_t a0 = sY[gid*SYW + ks*8 + tig];
            uint32_t a1 = sY[(gid+8)*SYW + ks*8 + tig];
            uint32_t a2 = sY[gid*SYW + ks*8 + tig + 4];
            uint32_t a3 = sY[(gid+8)*SYW + ks*8 + tig + 4];
#pragma unroll
            for (int nt = 0; nt < 4; nt++) {
                int n = wn2 + nt*8 + gid;
                uint32_t b0 = __ldg(Wn + n*(FOUT/2) + ks*8 + tig);
                uint32_t b1 = __ldg(Wn + n*(FOUT/2) + ks*8 + tig + 4);
                MMA_F16(acc2[nt], a0, a1, a2, a3, b0, b1);
            }
        }

        __half* dst = (__half*)XWT_out;
#pragma unroll
        for (int nt = 0; nt < 4; nt++) {
            int col = wn2 + nt*8 + 2*tig;
            if (r0 < NN) {
                dst[((size_t)b*128 + col    )*160 + r0] = __float2half(acc2[nt][0]);
                dst[((size_t)b*128 + col + 1)*160 + r0] = __float2half(acc2[nt][1]);
            }
            if (r1 < NN) {
                dst[((size_t)b*128 + col    )*160 + r1] = __float2half(acc2[nt][2]);
                dst[((size_t)b*128 + col + 1)*160 + r1] = __float2half(acc2[nt][3]);
            }
        }
    }
}

// ---------------- mean pool + policy head ------------------------------------
__global__ void head_kernel(const float* __restrict__ Y,
                            const float* __restrict__ pw,
                            const float* __restrict__ pb,
                            float* __restrict__ out) {
    int b = blockIdx.x;
    __shared__ float sp[128];
    int f = threadIdx.x;
    float s = 0.0f;
    const float* yb = Y + (size_t)b*NN*128;
    for (int n = 0; n < NN; n++) s += yb[n*128 + f];
    sp[f] = s * (1.0f / NN);
    __syncthreads();
    if (f < 5) {
        float a = pb[f];
#pragma unroll
        for (int i = 0; i < 128; i++) a += sp[i] * pw[i*5 + f];
        out[b*5 + f] = a;
    }
}

// ---------------- launch -----------------------------------------------------
extern "C" void kernel_launch(void* const* d_in, const int* in_sizes, int n_in,
                              void* d_out, int out_size) {
    const float* obs      = (const float*)d_in[0];
    const float* conv1_w  = (const float*)d_in[1];
    const float* conv1_b  = (const float*)d_in[2];
    const float* conv2_w  = (const float*)d_in[3];
    const float* conv2_b  = (const float*)d_in[4];
    const float* gcn1_w   = (const float*)d_in[5];
    const float* gcn1_b   = (const float*)d_in[6];
    const float* gcn2_w   = (const float*)d_in[7];
    const float* gcn2_b   = (const float*)d_in[8];
    const float* gcn3_w   = (const float*)d_in[9];
    const float* gcn3_b   = (const float*)d_in[10];
    const float* policy_w = (const float*)d_in[11];
    const float* policy_b = (const float*)d_in[12];
    float* out = (float*)d_out;

    float *fa;
    uint32_t *xwA, *xwB, *wg2, *wg3;
    cudaGetSymbolAddress((void**)&fa, g_fa);
    cudaGetSymbolAddress((void**)&xwA, g_xwTA);
    cudaGetSymbolAddress((void**)&xwB, g_xwTB);
    cudaGetSymbolAddress((void**)&wg2, g_wg2);
    cudaGetSymbolAddress((void**)&wg3, g_wg3);

    prep_a<<<9, 256>>>(conv1_w, conv2_w);
    prep_b<<<32, 256>>>(gcn1_w, gcn3_w);
    prep_c<<<16, 256>>>(gcn2_w);
    conv_fused_kernel<<<dim3(10, 19, BB), 128>>>(obs, conv1_b, conv2_b);   // #4
    deg_kernel<<<BB*NN, 128>>>();

    xw1_kernel<<<147, 128>>>();
    gcn_kernel<64,  false><<<dim3(10, BB), 128>>>(xwA, gcn1_b, wg2, xwB, nullptr);
    gcn_kernel<128, false><<<dim3(10, BB), 128>>>(xwB, gcn2_b, wg3, xwA, nullptr);
    gcn_kernel<128, true ><<<dim3(10, BB), 128>>>(xwA, gcn3_b, nullptr, nullptr, fa);

    head_kernel<<<BB, 128>>>(fa, policy_w, policy_b, out);
}

// round 9
// speedup vs baseline: 1.5738x; 1.1600x over previous
#include <cuda_runtime.h>
#include <cuda_fp16.h>
#include <cstdint>

#define BB 64
#define NN 147
#define NSQ (NN*NN)          // 21609

// ---------------- scratch (device globals; zero-initialized) -----------------
__device__ float g_ahat[(size_t)BB * NSQ];      // A_hat (unnormalized) [b][t][s]
__device__ float g_dinv[BB * NN];
__device__ uint32_t g_x0h[(size_t)BB * NN * 16];     // node feats fp16 [node][16 words]
__device__ uint32_t g_xwTA[(size_t)BB * 128 * 80];   // XW^T fp16 [b][f][160 s] ping
__device__ uint32_t g_xwTB[(size_t)BB * 128 * 80];   // pong (pads stay zero)
__device__ float g_fa[(size_t)BB * NN * 128];   // final GCN output (fp32)

__device__ uint32_t g_w2h[9*32*12];  // conv2 w fp16: [(tap*32+o)*12 + q], q=ci/2
__device__ uint32_t g_w1t[32*16];    // conv1 w tf32: [k][o], k>=27 -> 0
__device__ uint32_t g_wg1[64*16];    // gcn1_w fp16 T: [n][q=k/2], K=32
__device__ uint32_t g_wg2[128*32];   // gcn2_w fp16 T: [n][q], K=64
__device__ uint32_t g_wg3[128*64];   // gcn3_w fp16 T: [n][q], K=128

__device__ __forceinline__ uint32_t f2tf32(float f) {
    uint32_t r;
    asm("cvt.rna.tf32.f32 %0, %1;" : "=r"(r) : "f"(f));
    return r;
}
__device__ __forceinline__ uint32_t packh2(float lo, float hi) {
    __half2 h = __floats2half2_rn(lo, hi);
    return *(uint32_t*)&h;
}

#define MMA_TF32(d, a0_, a1_, a2_, a3_, b0_, b1_)                              \
    asm volatile("mma.sync.aligned.m16n8k8.row.col.f32.tf32.tf32.f32 "         \
                 "{%0,%1,%2,%3}, {%4,%5,%6,%7}, {%8,%9}, {%0,%1,%2,%3};"       \
                 : "+f"((d)[0]), "+f"((d)[1]), "+f"((d)[2]), "+f"((d)[3])      \
                 : "r"(a0_), "r"(a1_), "r"(a2_), "r"(a3_), "r"(b0_), "r"(b1_))

#define MMA_F16(d, a0_, a1_, a2_, a3_, b0_, b1_)                               \
    asm volatile("mma.sync.aligned.m16n8k16.row.col.f32.f16.f16.f32 "          \
                 "{%0,%1,%2,%3}, {%4,%5,%6,%7}, {%8,%9}, {%0,%1,%2,%3};"       \
                 : "+f"((d)[0]), "+f"((d)[1]), "+f"((d)[2]), "+f"((d)[3])      \
                 : "r"(a0_), "r"(a1_), "r"(a2_), "r"(a3_), "r"(b0_), "r"(b1_))

// ---------------- one-time weight relayout/convert ---------------------------
__global__ void prep_a(const float* __restrict__ w1, const float* __restrict__ w2) {
    int i = blockIdx.x * 256 + threadIdx.x;
    if (i < 2304) {                      // conv2 -> fp16 pairs
        int tap = i >> 8, rem = i & 255, o = rem >> 3, q = rem & 7;
        g_w2h[(tap*32 + o)*12 + q] =
            packh2(w2[(o*16 + 2*q)*9 + tap], w2[(o*16 + 2*q + 1)*9 + tap]);
    }
    if (i < 512) {                       // conv1 -> tf32, k>=27 zero
        int k = i >> 4, o = i & 15;
        uint32_t v = 0u;
        if (k < 27) {
            int tap = (k*11) >> 5, c = k - 3*tap;
            int kh = (tap*11) >> 5, kw = tap - 3*kh;
            v = f2tf32(w1[((o*3 + c)*3 + kh)*3 + kw]);   // OIHW
        }
        g_w1t[i] = v;
    }
}
__global__ void prep_b(const float* __restrict__ wg1, const float* __restrict__ wg3) {
    int i = blockIdx.x * 256 + threadIdx.x;
    if (i < 1024) {
        int n = i >> 4, q = i & 15;
        g_wg1[i] = packh2(wg1[2*q*64 + n], wg1[(2*q + 1)*64 + n]);
    }
    if (i < 8192) {
        int n = i >> 6, q = i & 63;
        g_wg3[i] = packh2(wg3[2*q*128 + n], wg3[(2*q + 1)*128 + n]);
    }
}
__global__ void prep_c(const float* __restrict__ wg2) {
    int i = blockIdx.x * 256 + threadIdx.x;
    if (i < 4096) {
        int n = i >> 5, q = i & 31;
        g_wg2[i] = packh2(wg2[2*q*128 + n], wg2[(2*q + 1)*128 + n]);
    }
}

// ====== fused conv1(3->16, tf32 MMA) + conv2(16->32, fp16 MMA) + epilogue ====
// grid: (5, 19, B). block = 256 threads = 8x32 output tile (warp = 1 img row).
#define PST 12                            // patch pixel stride (words, half2)
#define PPX 340                           // patch pixels: 10 rows x 34 cols
__global__ void __launch_bounds__(256)
conv_fused_kernel(const float* __restrict__ obs,
                  const float* __restrict__ b1,
                  const float* __restrict__ b2) {
    __shared__ uint32_t sW2h[9*32*12];    // 13.8 KB
    __shared__ uint32_t sPu[PPX*PST];     // 16.3 KB fp16 h1 patch
    __shared__ uint32_t sObs32[1408];     // 12x36x3 tf32 + zero pad
    __shared__ uint32_t sW1u[512];
    __shared__ float sb1[16];

    int tid = threadIdx.x;
    int lane = tid & 31, warp = tid >> 5;
    int gid = lane >> 2, tig = lane & 3;
    int b   = blockIdx.z;
    int bw0 = blockIdx.x * 32;
    int bh0 = blockIdx.y * 8;

    {   // stage weights: coalesced copies
        uint4* dst = (uint4*)sW2h;
        const uint4* src = (const uint4*)g_w2h;
        for (int i = tid; i < 9*32*12/4; i += 256) dst[i] = src[i];
        if (tid < 128) ((uint4*)sW1u)[tid] = ((const uint4*)g_w1t)[tid];
    }
    if (tid < 16) sb1[tid] = b1[tid];
    if (tid >= 144 && tid < 256) sObs32[1296 + tid - 144] = 0u;   // pad finite

    // obs halo patch (tf32): rows bh0-2..bh0+9, cols bw0-2..bw0+33
    for (int i = tid; i < 1296; i += 256) {
        int pr = i / 108, within = i - pr*108;
        int hi = bh0 + pr - 2;
        int wi = bw0 - 2 + within/3;
        float v = 0.0f;
        if (hi >= 0 && hi < NN && wi >= 0 && wi < NN)
            v = obs[(size_t)(b*NN + hi)*NN*3 + (bw0 - 2)*3 + within];
        sObs32[i] = f2tf32(v);
    }
    __syncthreads();

    // ---------- conv1 via tf32 MMA: A = 384 px x K32 im2col, B = w1 ---------
    {
        int offA[4][2];
#pragma unroll
        for (int ks = 0; ks < 4; ks++) {
#pragma unroll
            for (int hh = 0; hh < 2; hh++) {
                int k = ks*8 + tig + hh*4;
                int tap = (k*11) >> 5, c = k - 3*tap;
                int kh = (tap*11) >> 5, kw = tap - 3*kh;
                offA[ks][hh] = kh*108 + kw*3 + c;
            }
        }

        float accP[3][2][4];
#pragma unroll
        for (int mt = 0; mt < 3; mt++)
#pragma unroll
            for (int nt = 0; nt < 2; nt++)
#pragma unroll
                for (int q = 0; q < 4; q++) accP[mt][nt][q] = 0.0f;

#pragma unroll
        for (int mt = 0; mt < 3; mt++) {
            int p1 = warp*48 + mt*16 + gid;
            int p2 = p1 + 8;
            int p1c = min(p1, PPX-1), p2c = min(p2, PPX-1);
            int pr1 = p1c / 34, pr2 = p2c / 34;
            int bp1 = pr1*108 + (p1c - pr1*34)*3;
            int bp2 = pr2*108 + (p2c - pr2*34)*3;
#pragma unroll
            for (int ks = 0; ks < 4; ks++) {
                uint32_t a0 = sObs32[bp1 + offA[ks][0]];
                uint32_t a1 = sObs32[bp2 + offA[ks][0]];
                uint32_t a2 = sObs32[bp1 + offA[ks][1]];
                uint32_t a3 = sObs32[bp2 + offA[ks][1]];
#pragma unroll
                for (int nt = 0; nt < 2; nt++) {
                    int n = nt*8 + gid;
                    uint32_t b0 = sW1u[(ks*8 + tig)*16 + n];
                    uint32_t b1v = sW1u[(ks*8 + tig + 4)*16 + n];
                    MMA_TF32(accP[mt][nt], a0, a1, a2, a3, b0, b1v);
                }
            }
        }

        // bias+relu, zero invalid pixels, pack fp16 pairs -> sPu
#pragma unroll
        for (int mt = 0; mt < 3; mt++) {
#pragma unroll
            for (int hp = 0; hp < 2; hp++) {
                int p = warp*48 + mt*16 + gid + hp*8;
                if (p < PPX) {
                    int pr = p / 34, pc = p - pr*34;
                    int hi = bh0 + pr - 1, wi = bw0 + pc - 1;
                    bool valid = (hi >= 0 && hi < NN && wi >= 0 && wi < NN);
#pragma unroll
                    for (int nt = 0; nt < 2; nt++) {
                        int ch = nt*8 + 2*tig;
                        float v0 = 0.0f, v1 = 0.0f;
                        if (valid) {
                            v0 = fmaxf(accP[mt][nt][hp*2]   + sb1[ch],   0.0f);
                            v1 = fmaxf(accP[mt][nt][hp*2+1] + sb1[ch+1], 0.0f);
                        }
                        sPu[p*PST + nt*4 + tig] = packh2(v0, v1);
                    }
                }
            }
        }
    }
    __syncthreads();

    // ---------- conv2 via fp16 MMA: one k16 chunk per tap --------------------
    // warp owns image row ph=warp; m-tile mt covers cols [mt*16, mt*16+16)
    float acc[2][4][4];
#pragma unroll
    for (int mt = 0; mt < 2; mt++)
#pragma unroll
        for (int nt = 0; nt < 4; nt++)
#pragma unroll
            for (int q = 0; q < 4; q++) acc[mt][nt][q] = 0.0f;

#pragma unroll
    for (int th = 0; th < 3; th++) {
#pragma unroll
        for (int tw = 0; tw < 3; tw++) {
            int tap = th*3 + tw;
            uint32_t bf[4][2];
#pragma unroll
            for (int nt = 0; nt < 4; nt++) {
                int o = nt*8 + gid;
                bf[nt][0] = sW2h[(tap*32 + o)*12 + tig];
                bf[nt][1] = sW2h[(tap*32 + o)*12 + tig + 4];
            }
#pragma unroll
            for (int mt = 0; mt < 2; mt++) {
                int P1 = (warp + th)*34 + mt*16 + gid + tw;
                uint32_t a0 = sPu[P1*PST + tig];
                uint32_t a1 = sPu[(P1+8)*PST + tig];
                uint32_t a2 = sPu[P1*PST + tig + 4];
                uint32_t a3 = sPu[(P1+8)*PST + tig + 4];
#pragma unroll
                for (int nt = 0; nt < 4; nt++)
                    MMA_F16(acc[mt][nt], a0, a1, a2, a3, bf[nt][0], bf[nt][1]);
            }
        }
    }

    // ---------- register epilogue: quad-shuffle channel mean -----------------
    {
        float bv[4][2];
#pragma unroll
        for (int nt = 0; nt < 4; nt++) {
            bv[nt][0] = __ldg(b2 + nt*8 + 2*tig);
            bv[nt][1] = __ldg(b2 + nt*8 + 2*tig + 1);
        }
        int h = bh0 + warp;
#pragma unroll
        for (int mt = 0; mt < 2; mt++) {
#pragma unroll
            for (int rh = 0; rh < 2; rh++) {
                float y[8];
                float s = 0.0f;
#pragma unroll
                for (int nt = 0; nt < 4; nt++) {
                    float u0 = fmaxf(acc[mt][nt][rh*2]   + bv[nt][0], 0.0f);
                    float u1 = fmaxf(acc[mt][nt][rh*2+1] + bv[nt][1], 0.0f);
                    y[nt*2] = u0; y[nt*2+1] = u1;
                    s += u0 + u1;
                }
                s += __shfl_xor_sync(0xffffffff, s, 1);
                s += __shfl_xor_sync(0xffffffff, s, 2);
                int wq = bw0 + mt*16 + gid + rh*8;
                if (h < NN && wq < NN) {
                    if (tig == 0)
                        g_ahat[(size_t)b*NSQ + (size_t)wq*NN + h] =
                            s * (1.0f/32.0f) + (h == wq ? 1.0f : 0.0f);
                    if (h == wq) {
                        uint32_t* xp = g_x0h + ((size_t)b*NN + h)*16;
#pragma unroll
                        for (int nt = 0; nt < 4; nt++)
                            xp[nt*4 + tig] = packh2(y[nt*2], y[nt*2+1]);
                    }
                }
            }
        }
    }
}

// ---------------- degree / D^-1/2 --------------------------------------------
__global__ void deg_kernel() {
    int bt = blockIdx.x;
    const float* row = g_ahat + (size_t)bt * NN;
    int tid = threadIdx.x;
    float s = 0.0f;
    for (int i = tid; i < NN; i += 128) s += row[i];
#pragma unroll
    for (int o = 16; o > 0; o >>= 1) s += __shfl_xor_sync(0xffffffff, s, o);
    __shared__ float ws[4];
    if ((tid & 31) == 0) ws[tid >> 5] = s;
    __syncthreads();
    if (tid == 0) {
        float d = ws[0] + ws[1] + ws[2] + ws[3];
        g_dinv[bt] = d > 0.0f ? rsqrtf(d) : 0.0f;
    }
}

// -------- XW1^T = (x0 @ W1)^T via fp16 MMA; out fp16 [b][f][160] -------------
__global__ void xw1_kernel() {
    int lane = threadIdx.x & 31, warp = threadIdx.x >> 5;
    int gid = lane >> 2, tig = lane & 3;
    int m0 = blockIdx.x * 64 + warp * 16;

    float acc[8][4];
#pragma unroll
    for (int nt = 0; nt < 8; nt++)
#pragma unroll
        for (int q = 0; q < 4; q++) acc[nt][q] = 0.0f;

    int r0 = m0 + gid, r1 = r0 + 8;
#pragma unroll
    for (int ks = 0; ks < 2; ks++) {
        uint32_t a0 = g_x0h[(size_t)r0*16 + ks*8 + tig];
        uint32_t a1 = g_x0h[(size_t)r1*16 + ks*8 + tig];
        uint32_t a2 = g_x0h[(size_t)r0*16 + ks*8 + tig + 4];
        uint32_t a3 = g_x0h[(size_t)r1*16 + ks*8 + tig + 4];
#pragma unroll
        for (int nt = 0; nt < 8; nt++) {
            int n = nt*8 + gid;
            uint32_t b0 = g_wg1[n*16 + ks*8 + tig];
            uint32_t b1 = g_wg1[n*16 + ks*8 + tig + 4];
            MMA_F16(acc[nt], a0, a1, a2, a3, b0, b1);
        }
    }

    __half* dst = (__half*)g_xwTA;
    int b0i = r0 / NN, s0 = r0 - b0i*NN;
    int b1i = r1 / NN, s1 = r1 - b1i*NN;
#pragma unroll
    for (int nt = 0; nt < 8; nt++) {
        int col = nt*8 + 2*tig;
        dst[((size_t)b0i*128 + col    )*160 + s0] = __float2half(acc[nt][0]);
        dst[((size_t)b0i*128 + col + 1)*160 + s0] = __float2half(acc[nt][1]);
        dst[((size_t)b1i*128 + col    )*160 + s1] = __float2half(acc[nt][2]);
        dst[((size_t)b1i*128 + col + 1)*160 + s1] = __float2half(acc[nt][3]);
    }
}

// --- GCN layer: Y = relu(norm @ XW_in^T' + b); then XW_out^T = (Y @ Wn)^T ----
template<int FOUT, bool LAST>
__global__ void __launch_bounds__(128)
gcn_kernel(const uint32_t* __restrict__ XWT_in,
           const float* __restrict__ bias,
           const uint32_t* __restrict__ Wn,
           uint32_t* __restrict__ XWT_out,
           float* __restrict__ Yout) {
    constexpr int NTW  = FOUT / 32;
    constexpr int SYW  = FOUT/2 + 4;
    __shared__ uint32_t sA[16 * 84];
    __shared__ float sds[160];
    __shared__ uint32_t sY[16 * SYW];

    int tid = threadIdx.x;
    int lane = tid & 31, warp = tid >> 5;
    int gid = lane >> 2, tig = lane & 3;
    int b = blockIdx.y, t0 = blockIdx.x * 16;

    for (int i = tid; i < 160; i += 128)
        sds[i] = (i < NN) ? g_dinv[b*NN + i] : 0.0f;
    __syncthreads();

    {
        __half* sAh = (__half*)sA;
        const float* ab = g_ahat + (size_t)b * NSQ;
        for (int i = tid; i < 16*168; i += 128) {
            int r = i / 168, s = i - r*168;
            int t = t0 + r;
            float v = 0.0f;
            if (t < NN && s < NN) v = ab[(size_t)t*NN + s] * sds[t] * sds[s];
            sAh[r*168 + s] = __float2half(v);
        }
    }
    __syncthreads();

    float acc[NTW][4];
#pragma unroll
    for (int nt = 0; nt < NTW; nt++)
#pragma unroll
        for (int q = 0; q < 4; q++) acc[nt][q] = 0.0f;

    int wn0 = warp * (FOUT/4);
    const uint32_t* xwb = XWT_in + (size_t)b * 128 * 80;

#pragma unroll
    for (int ks = 0; ks < 10; ks++) {
        uint32_t a0 = sA[gid*84 + ks*8 + tig];
        uint32_t a1 = sA[(gid+8)*84 + ks*8 + tig];
        uint32_t a2 = sA[gid*84 + ks*8 + tig + 4];
        uint32_t a3 = sA[(gid+8)*84 + ks*8 + tig + 4];
#pragma unroll
        for (int nt = 0; nt < NTW; nt++) {
            int n = wn0 + nt*8 + gid;
            uint32_t b0 = __ldg(xwb + (size_t)n*80 + ks*8 + tig);
            uint32_t b1 = __ldg(xwb + (size_t)n*80 + ks*8 + tig + 4);
            MMA_F16(acc[nt], a0, a1, a2, a3, b0, b1);
        }
    }

    int r0 = t0 + gid, r1 = r0 + 8;
#pragma unroll
    for (int nt = 0; nt < NTW; nt++) {
        int col = wn0 + nt*8 + 2*tig;
        float bv0 = __ldg(bias + col), bv1 = __ldg(bias + col + 1);
        float y00 = fmaxf(acc[nt][0] + bv0, 0.0f);
        float y01 = fmaxf(acc[nt][1] + bv1, 0.0f);
        float y10 = fmaxf(acc[nt][2] + bv0, 0.0f);
        float y11 = fmaxf(acc[nt][3] + bv1, 0.0f);
        if (LAST) {
            if (r0 < NN)
                *(float2*)&Yout[(size_t)(b*NN + r0)*FOUT + col] = make_float2(y00, y01);
            if (r1 < NN)
                *(float2*)&Yout[(size_t)(b*NN + r1)*FOUT + col] = make_float2(y10, y11);
        } else {
            int wq = wn0/2 + nt*4 + tig;
            sY[gid*SYW + wq]     = packh2(y00, y01);
            sY[(gid+8)*SYW + wq] = packh2(y10, y11);
        }
    }

    if (!LAST) {
        __syncthreads();

        float acc2[4][4];
#pragma unroll
        for (int nt = 0; nt < 4; nt++)
#pragma unroll
            for (int q = 0; q < 4; q++) acc2[nt][q] = 0.0f;

        int wn2 = warp * 32;
#pragma unroll
        for (int ks = 0; ks < FOUT/16; ks++) {
            uint32_t a0 = sY[gid*SYW + ks*8 + tig];
            uint32_t a1 = sY[(gid+8)*SYW + ks*8 + tig];
            uint32_t a2 = sY[gid*SYW + ks*8 + tig + 4];
            uint32_t a3 = sY[(gid+8)*SYW + ks*8 + tig + 4];
#pragma unroll
            for (int nt = 0; nt < 4; nt++) {
                int n = wn2 + nt*8 + gid;
                uint32_t b0 = __ldg(Wn + n*(FOUT/2) + ks*8 + tig);
                uint32_t b1 = __ldg(Wn + n*(FOUT/2) + ks*8 + tig + 4);
                MMA_F16(acc2[nt], a0, a1, a2, a3, b0, b1);
            }
        }

        __half* dst = (__half*)XWT_out;
#pragma unroll
        for (int nt = 0; nt < 4; nt++) {
            int col = wn2 + nt*8 + 2*tig;
            if (r0 < NN) {
                dst[((size_t)b*128 + col    )*160 + r0] = __float2half(acc2[nt][0]);
                dst[((size_t)b*128 + col + 1)*160 + r0] = __float2half(acc2[nt][1]);
            }
            if (r1 < NN) {
                dst[((size_t)b*128 + col    )*160 + r1] = __float2half(acc2[nt][2]);
                dst[((size_t)b*128 + col + 1)*160 + r1] = __float2half(acc2[nt][3]);
            }
        }
    }
}

// ---------------- mean pool + policy head ------------------------------------
__global__ void head_kernel(const float* __restrict__ Y,
                            const float* __restrict__ pw,
                            const float* __restrict__ pb,
                            float* __restrict__ out) {
    int b = blockIdx.x;
    __shared__ float sp[128];
    int f = threadIdx.x;
    float s = 0.0f;
    const float* yb = Y + (size_t)b*NN*128;
    for (int n = 0; n < NN; n++) s += yb[n*128 + f];
    sp[f] = s * (1.0f / NN);
    __syncthreads();
    if (f < 5) {
        float a = pb[f];
#pragma unroll
        for (int i = 0; i < 128; i++) a += sp[i] * pw[i*5 + f];
        out[b*5 + f] = a;
    }
}

// ---------------- launch -----------------------------------------------------
extern "C" void kernel_launch(void* const* d_in, const int* in_sizes, int n_in,
                              void* d_out, int out_size) {
    const float* obs      = (const float*)d_in[0];
    const float* conv1_w  = (const float*)d_in[1];
    const float* conv1_b  = (const float*)d_in[2];
    const float* conv2_w  = (const float*)d_in[3];
    const float* conv2_b  = (const float*)d_in[4];
    const float* gcn1_w   = (const float*)d_in[5];
    const float* gcn1_b   = (const float*)d_in[6];
    const float* gcn2_w   = (const float*)d_in[7];
    const float* gcn2_b   = (const float*)d_in[8];
    const float* gcn3_w   = (const float*)d_in[9];
    const float* gcn3_b   = (const float*)d_in[10];
    const float* policy_w = (const float*)d_in[11];
    const float* policy_b = (const float*)d_in[12];
    float* out = (float*)d_out;

    float *fa;
    uint32_t *xwA, *xwB, *wg2, *wg3;
    cudaGetSymbolAddress((void**)&fa, g_fa);
    cudaGetSymbolAddress((void**)&xwA, g_xwTA);
    cudaGetSymbolAddress((void**)&xwB, g_xwTB);
    cudaGetSymbolAddress((void**)&wg2, g_wg2);
    cudaGetSymbolAddress((void**)&wg3, g_wg3);

    prep_a<<<9, 256>>>(conv1_w, conv2_w);
    prep_b<<<32, 256>>>(gcn1_w, gcn3_w);
    prep_c<<<16, 256>>>(gcn2_w);
    conv_fused_kernel<<<dim3(5, 19, BB), 256>>>(obs, conv1_b, conv2_b);   // #4
    deg_kernel<<<BB*NN, 128>>>();

    xw1_kernel<<<147, 128>>>();
    gcn_kernel<64,  false><<<dim3(10, BB), 128>>>(xwA, gcn1_b, wg2, xwB, nullptr);
    gcn_kernel<128, false><<<dim3(10, BB), 128>>>(xwB, gcn2_b, wg3, xwA, nullptr);
    gcn_kernel<128, true ><<<dim3(10, BB), 128>>>(xwA, gcn3_b, nullptr, nullptr, fa);

    head_kernel<<<BB, 128>>>(fa, policy_w, policy_b, out);
}

// round 10
// speedup vs baseline: 1.6166x; 1.0272x over previous
#include <cuda_runtime.h>
#include <cuda_fp16.h>
#include <cstdint>

#define BB 64
#define NN 147
#define NSQ (NN*NN)          // 21609

// ---------------- scratch (device globals; zero-initialized) -----------------
__device__ float g_ahat[(size_t)BB * NSQ];      // A_hat (unnormalized) [b][t][s]
__device__ float g_dinv[BB * NN];
__device__ uint32_t g_x0h[(size_t)BB * NN * 16];     // node feats fp16 [node][16 words]
__device__ uint32_t g_xwTA[(size_t)BB * 128 * 80];   // XW^T fp16 [b][f][160 s] ping
__device__ uint32_t g_xwTB[(size_t)BB * 128 * 80];   // pong (pads stay zero)
__device__ float g_fa[(size_t)BB * NN * 128];   // final GCN output (fp32)

__device__ uint32_t g_w2h[9*32*8];   // conv2 w fp16, k-pair interleaved:
                                     // [(tap*32+o)*8 + 2t + hi] = ci{2t+8hi, +1}
__device__ uint32_t g_w1t[32*16];    // conv1 w tf32: [k][o], k>=27 -> 0
__device__ uint32_t g_wg1[64*16];    // gcn1_w fp16 T: [n][q=k/2], K=32
__device__ uint32_t g_wg2[128*32];   // gcn2_w fp16 T: [n][q], K=64
__device__ uint32_t g_wg3[128*64];   // gcn3_w fp16 T: [n][q], K=128

__device__ __forceinline__ uint32_t f2tf32(float f) {
    uint32_t r;
    asm("cvt.rna.tf32.f32 %0, %1;" : "=r"(r) : "f"(f));
    return r;
}
__device__ __forceinline__ uint32_t packh2(float lo, float hi) {
    __half2 h = __floats2half2_rn(lo, hi);
    return *(uint32_t*)&h;
}

#define MMA_TF32(d, a0_, a1_, a2_, a3_, b0_, b1_)                              \
    asm volatile("mma.sync.aligned.m16n8k8.row.col.f32.tf32.tf32.f32 "         \
                 "{%0,%1,%2,%3}, {%4,%5,%6,%7}, {%8,%9}, {%0,%1,%2,%3};"       \
                 : "+f"((d)[0]), "+f"((d)[1]), "+f"((d)[2]), "+f"((d)[3])      \
                 : "r"(a0_), "r"(a1_), "r"(a2_), "r"(a3_), "r"(b0_), "r"(b1_))

#define MMA_F16(d, a0_, a1_, a2_, a3_, b0_, b1_)                               \
    asm volatile("mma.sync.aligned.m16n8k16.row.col.f32.f16.f16.f32 "          \
                 "{%0,%1,%2,%3}, {%4,%5,%6,%7}, {%8,%9}, {%0,%1,%2,%3};"       \
                 : "+f"((d)[0]), "+f"((d)[1]), "+f"((d)[2]), "+f"((d)[3])      \
                 : "r"(a0_), "r"(a1_), "r"(a2_), "r"(a3_), "r"(b0_), "r"(b1_))

// ---------------- one-time weight relayout/convert (single kernel) -----------
__global__ void prep_kernel(const float* __restrict__ w1,
                            const float* __restrict__ w2,
                            const float* __restrict__ wg1,
                            const float* __restrict__ wg2,
                            const float* __restrict__ wg3) {
    int i = blockIdx.x * 256 + threadIdx.x;
    if (i < 2304) {                      // conv2 -> fp16, k-pair interleaved
        int row = i >> 3, j = i & 7;
        int tap = row >> 5, o = row & 31;
        int ci0 = 2*(j >> 1) + (j & 1)*8;
        g_w2h[i] = packh2(w2[(o*16 + ci0)*9 + tap], w2[(o*16 + ci0 + 1)*9 + tap]);
    }
    if (i < 512) {                       // conv1 -> tf32, k>=27 zero
        int k = i >> 4, o = i & 15;
        uint32_t v = 0u;
        if (k < 27) {
            int tap = (k*11) >> 5, c = k - 3*tap;
            int kh = (tap*11) >> 5, kw = tap - 3*kh;
            v = f2tf32(w1[((o*3 + c)*3 + kh)*3 + kw]);   // OIHW
        }
        g_w1t[i] = v;
    }
    if (i < 1024) {
        int n = i >> 4, q = i & 15;
        g_wg1[i] = packh2(wg1[2*q*64 + n], wg1[(2*q + 1)*64 + n]);
    }
    if (i < 4096) {
        int n = i >> 5, q = i & 31;
        g_wg2[i] = packh2(wg2[2*q*128 + n], wg2[(2*q + 1)*128 + n]);
    }
    if (i < 8192) {
        int n = i >> 6, q = i & 63;
        g_wg3[i] = packh2(wg3[2*q*128 + n], wg3[(2*q + 1)*128 + n]);
    }
}

// ====== fused conv1(3->16, tf32 MMA) + conv2(16->32, fp16 MMA) + epilogue ====
// grid: (5, 19, B). block = 256 threads = 8x32 output tile (warp = 1 img row).
#define PST 8                             // patch pixel stride (words), k-interleaved
#define PPX 340                           // patch pixels: 10 rows x 34 cols
__global__ void __launch_bounds__(256)
conv_fused_kernel(const float* __restrict__ obs,
                  const float* __restrict__ b1,
                  const float* __restrict__ b2) {
    __shared__ uint32_t sW2h[9*32*8];     // 9.2 KB
    __shared__ uint32_t sPu[PPX*PST];     // 10.9 KB fp16 h1 patch (k-interleaved)
    __shared__ uint32_t sObs32[1408];     // 12x36x3 tf32 + zero pad
    __shared__ uint32_t sW1u[512];
    __shared__ float sb1[16];

    int tid = threadIdx.x;
    int lane = tid & 31, warp = tid >> 5;
    int gid = lane >> 2, tig = lane & 3;
    int b   = blockIdx.z;
    int bw0 = blockIdx.x * 32;
    int bh0 = blockIdx.y * 8;

    {   // stage weights: coalesced copies
        uint4* dst = (uint4*)sW2h;
        const uint4* src = (const uint4*)g_w2h;
        for (int i = tid; i < 576; i += 256) dst[i] = src[i];
        if (tid < 128) ((uint4*)sW1u)[tid] = ((const uint4*)g_w1t)[tid];
    }
    if (tid < 16) sb1[tid] = b1[tid];
    if (tid >= 144 && tid < 256) sObs32[1296 + tid - 144] = 0u;   // pad finite

    // obs halo patch (tf32): rows bh0-2..bh0+9, cols bw0-2..bw0+33
    for (int i = tid; i < 1296; i += 256) {
        int pr = i / 108, within = i - pr*108;
        int hi = bh0 + pr - 2;
        int wi = bw0 - 2 + within/3;
        float v = 0.0f;
        if (hi >= 0 && hi < NN && wi >= 0 && wi < NN)
            v = obs[(size_t)(b*NN + hi)*NN*3 + (bw0 - 2)*3 + within];
        sObs32[i] = f2tf32(v);
    }
    __syncthreads();

    // ---------- conv1 via tf32 MMA: A = 384 px x K32 im2col, B = w1 ---------
    {
        int offA[4][2];
#pragma unroll
        for (int ks = 0; ks < 4; ks++) {
#pragma unroll
            for (int hh = 0; hh < 2; hh++) {
                int k = ks*8 + tig + hh*4;
                int tap = (k*11) >> 5, c = k - 3*tap;
                int kh = (tap*11) >> 5, kw = tap - 3*kh;
                offA[ks][hh] = kh*108 + kw*3 + c;
            }
        }

        float accP[3][2][4];
#pragma unroll
        for (int mt = 0; mt < 3; mt++)
#pragma unroll
            for (int nt = 0; nt < 2; nt++)
#pragma unroll
                for (int q = 0; q < 4; q++) accP[mt][nt][q] = 0.0f;

#pragma unroll
        for (int mt = 0; mt < 3; mt++) {
            int p1 = warp*48 + mt*16 + gid;
            int p2 = p1 + 8;
            int p1c = min(p1, PPX-1), p2c = min(p2, PPX-1);
            int pr1 = p1c / 34, pr2 = p2c / 34;
            int bp1 = pr1*108 + (p1c - pr1*34)*3;
            int bp2 = pr2*108 + (p2c - pr2*34)*3;
#pragma unroll
            for (int ks = 0; ks < 4; ks++) {
                uint32_t a0 = sObs32[bp1 + offA[ks][0]];
                uint32_t a1 = sObs32[bp2 + offA[ks][0]];
                uint32_t a2 = sObs32[bp1 + offA[ks][1]];
                uint32_t a3 = sObs32[bp2 + offA[ks][1]];
#pragma unroll
                for (int nt = 0; nt < 2; nt++) {
                    int n = nt*8 + gid;
                    uint32_t b0 = sW1u[(ks*8 + tig)*16 + n];
                    uint32_t b1v = sW1u[(ks*8 + tig + 4)*16 + n];
                    MMA_TF32(accP[mt][nt], a0, a1, a2, a3, b0, b1v);
                }
            }
        }

        // bias+relu, zero invalid pixels, STS.64 k-pair interleaved
#pragma unroll
        for (int mt = 0; mt < 3; mt++) {
#pragma unroll
            for (int hp = 0; hp < 2; hp++) {
                int p = warp*48 + mt*16 + gid + hp*8;
                if (p < PPX) {
                    int pr = p / 34, pc = p - pr*34;
                    int hi = bh0 + pr - 1, wi = bw0 + pc - 1;
                    bool valid = (hi >= 0 && hi < NN && wi >= 0 && wi < NN);
                    uint32_t wlo = 0u, whi = 0u;
                    if (valid) {
                        int ch0 = 2*tig;           // nt = 0
                        int ch1 = 8 + 2*tig;       // nt = 1
                        wlo = packh2(fmaxf(accP[mt][0][hp*2]   + sb1[ch0],   0.0f),
                                     fmaxf(accP[mt][0][hp*2+1] + sb1[ch0+1], 0.0f));
                        whi = packh2(fmaxf(accP[mt][1][hp*2]   + sb1[ch1],   0.0f),
                                     fmaxf(accP[mt][1][hp*2+1] + sb1[ch1+1], 0.0f));
                    }
                    ((uint2*)sPu)[p*4 + tig] = make_uint2(wlo, whi);
                }
            }
        }
    }
    __syncthreads();

    // ---------- conv2 via fp16 MMA: one k16 chunk per tap, LDS.64 frags ------
    float acc[2][4][4];
#pragma unroll
    for (int mt = 0; mt < 2; mt++)
#pragma unroll
        for (int nt = 0; nt < 4; nt++)
#pragma unroll
            for (int q = 0; q < 4; q++) acc[mt][nt][q] = 0.0f;

    const uint2* sPu2 = (const uint2*)sPu;
    const uint2* sW2  = (const uint2*)sW2h;

#pragma unroll
    for (int th = 0; th < 3; th++) {
#pragma unroll
        for (int tw = 0; tw < 3; tw++) {
            int tap = th*3 + tw;
            uint2 bf[4];
#pragma unroll
            for (int nt = 0; nt < 4; nt++)
                bf[nt] = sW2[(tap*32 + nt*8 + gid)*4 + tig];
#pragma unroll
            for (int mt = 0; mt < 2; mt++) {
                int P1 = (warp + th)*34 + mt*16 + gid + tw;
                uint2 A0 = sPu2[P1*4 + tig];
                uint2 A1 = sPu2[(P1+8)*4 + tig];
#pragma unroll
                for (int nt = 0; nt < 4; nt++)
                    MMA_F16(acc[mt][nt], A0.x, A1.x, A0.y, A1.y,
                            bf[nt].x, bf[nt].y);
            }
        }
    }

    // ---------- register epilogue: quad-shuffle channel mean -----------------
    {
        float bv[4][2];
#pragma unroll
        for (int nt = 0; nt < 4; nt++) {
            bv[nt][0] = __ldg(b2 + nt*8 + 2*tig);
            bv[nt][1] = __ldg(b2 + nt*8 + 2*tig + 1);
        }
        int h = bh0 + warp;
#pragma unroll
        for (int mt = 0; mt < 2; mt++) {
#pragma unroll
            for (int rh = 0; rh < 2; rh++) {
                float y[8];
                float s = 0.0f;
#pragma unroll
                for (int nt = 0; nt < 4; nt++) {
                    float u0 = fmaxf(acc[mt][nt][rh*2]   + bv[nt][0], 0.0f);
                    float u1 = fmaxf(acc[mt][nt][rh*2+1] + bv[nt][1], 0.0f);
                    y[nt*2] = u0; y[nt*2+1] = u1;
                    s += u0 + u1;
                }
                s += __shfl_xor_sync(0xffffffff, s, 1);
                s += __shfl_xor_sync(0xffffffff, s, 2);
                int wq = bw0 + mt*16 + gid + rh*8;
                if (h < NN && wq < NN) {
                    if (tig == 0)
                        g_ahat[(size_t)b*NSQ + (size_t)wq*NN + h] =
                            s * (1.0f/32.0f) + (h == wq ? 1.0f : 0.0f);
                    if (h == wq) {
                        uint32_t* xp = g_x0h + ((size_t)b*NN + h)*16;
#pragma unroll
                        for (int nt = 0; nt < 4; nt++)
                            xp[nt*4 + tig] = packh2(y[nt*2], y[nt*2+1]);
                    }
                }
            }
        }
    }
}

// ------ merged: deg (blocks >= 147) + XW1^T fp16 MMA (blocks 0..146) ---------
__global__ void xwdeg_kernel() {
    if (blockIdx.x >= 147) {
        // degree / D^-1/2 for one A_hat row
        int bt = blockIdx.x - 147;
        const float* row = g_ahat + (size_t)bt * NN;
        int tid = threadIdx.x;
        float s = 0.0f;
        for (int i = tid; i < NN; i += 128) s += row[i];
#pragma unroll
        for (int o = 16; o > 0; o >>= 1) s += __shfl_xor_sync(0xffffffff, s, o);
        __shared__ float ws[4];
        if ((tid & 31) == 0) ws[tid >> 5] = s;
        __syncthreads();
        if (tid == 0) {
            float d = ws[0] + ws[1] + ws[2] + ws[3];
            g_dinv[bt] = d > 0.0f ? rsqrtf(d) : 0.0f;
        }
        return;
    }

    int lane = threadIdx.x & 31, warp = threadIdx.x >> 5;
    int gid = lane >> 2, tig = lane & 3;
    int m0 = blockIdx.x * 64 + warp * 16;

    float acc[8][4];
#pragma unroll
    for (int nt = 0; nt < 8; nt++)
#pragma unroll
        for (int q = 0; q < 4; q++) acc[nt][q] = 0.0f;

    int r0 = m0 + gid, r1 = r0 + 8;
#pragma unroll
    for (int ks = 0; ks < 2; ks++) {
        uint32_t a0 = g_x0h[(size_t)r0*16 + ks*8 + tig];
        uint32_t a1 = g_x0h[(size_t)r1*16 + ks*8 + tig];
        uint32_t a2 = g_x0h[(size_t)r0*16 + ks*8 + tig + 4];
        uint32_t a3 = g_x0h[(size_t)r1*16 + ks*8 + tig + 4];
#pragma unroll
        for (int nt = 0; nt < 8; nt++) {
            int n = nt*8 + gid;
            uint32_t b0 = g_wg1[n*16 + ks*8 + tig];
            uint32_t b1 = g_wg1[n*16 + ks*8 + tig + 4];
            MMA_F16(acc[nt], a0, a1, a2, a3, b0, b1);
        }
    }

    __half* dst = (__half*)g_xwTA;
    int b0i = r0 / NN, s0 = r0 - b0i*NN;
    int b1i = r1 / NN, s1 = r1 - b1i*NN;
#pragma unroll
    for (int nt = 0; nt < 8; nt++) {
        int col = nt*8 + 2*tig;
        dst[((size_t)b0i*128 + col    )*160 + s0] = __float2half(acc[nt][0]);
        dst[((size_t)b0i*128 + col + 1)*160 + s0] = __float2half(acc[nt][1]);
        dst[((size_t)b1i*128 + col    )*160 + s1] = __float2half(acc[nt][2]);
        dst[((size_t)b1i*128 + col + 1)*160 + s1] = __float2half(acc[nt][3]);
    }
}

// --- GCN layer: Y = relu(norm @ XW_in^T' + b); then XW_out^T = (Y @ Wn)^T ----
template<int FOUT, bool LAST>
__global__ void __launch_bounds__(128)
gcn_kernel(const uint32_t* __restrict__ XWT_in,
           const float* __restrict__ bias,
           const uint32_t* __restrict__ Wn,
           uint32_t* __restrict__ XWT_out,
           float* __restrict__ Yout) {
    constexpr int NTW  = FOUT / 32;
    constexpr int SYW  = FOUT/2 + 4;
    __shared__ uint32_t sA[16 * 84];
    __shared__ float sds[160];
    __shared__ uint32_t sY[16 * SYW];

    int tid = threadIdx.x;
    int lane = tid & 31, warp = tid >> 5;
    int gid = lane >> 2, tig = lane & 3;
    int b = blockIdx.y, t0 = blockIdx.x * 16;

    for (int i = tid; i < 160; i += 128)
        sds[i] = (i < NN) ? g_dinv[b*NN + i] : 0.0f;
    __syncthreads();

    {
        __half* sAh = (__half*)sA;
        const float* ab = g_ahat + (size_t)b * NSQ;
        for (int i = tid; i < 16*168; i += 128) {
            int r = i / 168, s = i - r*168;
            int t = t0 + r;
            float v = 0.0f;
            if (t < NN && s < NN) v = ab[(size_t)t*NN + s] * sds[t] * sds[s];
            sAh[r*168 + s] = __float2half(v);
        }
    }
    __syncthreads();

    float acc[NTW][4];
#pragma unroll
    for (int nt = 0; nt < NTW; nt++)
#pragma unroll
        for (int q = 0; q < 4; q++) acc[nt][q] = 0.0f;

    int wn0 = warp * (FOUT/4);
    const uint32_t* xwb = XWT_in + (size_t)b * 128 * 80;

#pragma unroll
    for (int ks = 0; ks < 10; ks++) {
        uint32_t a0 = sA[gid*84 + ks*8 + tig];
        uint32_t a1 = sA[(gid+8)*84 + ks*8 + tig];
        uint32_t a2 = sA[gid*84 + ks*8 + tig + 4];
        uint32_t a3 = sA[(gid+8)*84 + ks*8 + tig + 4];
#pragma unroll
        for (int nt = 0; nt < NTW; nt++) {
            int n = wn0 + nt*8 + gid;
            uint32_t b0 = __ldg(xwb + (size_t)n*80 + ks*8 + tig);
            uint32_t b1 = __ldg(xwb + (size_t)n*80 + ks*8 + tig + 4);
            MMA_F16(acc[nt], a0, a1, a2, a3, b0, b1);
        }
    }

    int r0 = t0 + gid, r1 = r0 + 8;
#pragma unroll
    for (int nt = 0; nt < NTW; nt++) {
        int col = wn0 + nt*8 + 2*tig;
        float bv0 = __ldg(bias + col), bv1 = __ldg(bias + col + 1);
        float y00 = fmaxf(acc[nt][0] + bv0, 0.0f);
        float y01 = fmaxf(acc[nt][1] + bv1, 0.0f);
        float y10 = fmaxf(acc[nt][2] + bv0, 0.0f);
        float y11 = fmaxf(acc[nt][3] + bv1, 0.0f);
        if (LAST) {
            if (r0 < NN)
                *(float2*)&Yout[(size_t)(b*NN + r0)*FOUT + col] = make_float2(y00, y01);
            if (r1 < NN)
                *(float2*)&Yout[(size_t)(b*NN + r1)*FOUT + col] = make_float2(y10, y11);
        } else {
            int wq = wn0/2 + nt*4 + tig;
            sY[gid*SYW + wq]     = packh2(y00, y01);
            sY[(gid+8)*SYW + wq] = packh2(y10, y11);
        }
    }

    if (!LAST) {
        __syncthreads();

        float acc2[4][4];
#pragma unroll
        for (int nt = 0; nt < 4; nt++)
#pragma unroll
            for (int q = 0; q < 4; q++) acc2[nt][q] = 0.0f;

        int wn2 = warp * 32;
#pragma unroll
        for (int ks = 0; ks < FOUT/16; ks++) {
            uint32_t a0 = sY[gid*SYW + ks*8 + tig];
            uint32_t a1 = sY[(gid+8)*SYW + ks*8 + tig];
            uint32_t a2 = sY[gid*SYW + ks*8 + tig + 4];
            uint32_t a3 = sY[(gid+8)*SYW + ks*8 + tig + 4];
#pragma unroll
            for (int nt = 0; nt < 4; nt++) {
                int n = wn2 + nt*8 + gid;
                uint32_t b0 = __ldg(Wn + n*(FOUT/2) + ks*8 + tig);
                uint32_t b1 = __ldg(Wn + n*(FOUT/2) + ks*8 + tig + 4);
                MMA_F16(acc2[nt], a0, a1, a2, a3, b0, b1);
            }
        }

        __half* dst = (__half*)XWT_out;
#pragma unroll
        for (int nt = 0; nt < 4; nt++) {
            int col = wn2 + nt*8 + 2*tig;
            if (r0 < NN) {
                dst[((size_t)b*128 + col    )*160 + r0] = __float2half(acc2[nt][0]);
                dst[((size_t)b*128 + col + 1)*160 + r0] = __float2half(acc2[nt][1]);
            }
            if (r1 < NN) {
                dst[((size_t)b*128 + col    )*160 + r1] = __float2half(acc2[nt][2]);
                dst[((size_t)b*128 + col + 1)*160 + r1] = __float2half(acc2[nt][3]);
            }
        }
    }
}

// ---------------- mean pool + policy head ------------------------------------
__global__ void head_kernel(const float* __restrict__ Y,
                            const float* __restrict__ pw,
                            const float* __restrict__ pb,
                            float* __restrict__ out) {
    int b = blockIdx.x;
    __shared__ float sp[128];
    int f = threadIdx.x;
    float s = 0.0f;
    const float* yb = Y + (size_t)b*NN*128;
    for (int n = 0; n < NN; n++) s += yb[n*128 + f];
    sp[f] = s * (1.0f / NN);
    __syncthreads();
    if (f < 5) {
        float a = pb[f];
#pragma unroll
        for (int i = 0; i < 128; i++) a += sp[i] * pw[i*5 + f];
        out[b*5 + f] = a;
    }
}

// ---------------- launch -----------------------------------------------------
extern "C" void kernel_launch(void* const* d_in, const int* in_sizes, int n_in,
                              void* d_out, int out_size) {
    const float* obs      = (const float*)d_in[0];
    const float* conv1_w  = (const float*)d_in[1];
    const float* conv1_b  = (const float*)d_in[2];
    const float* conv2_w  = (const float*)d_in[3];
    const float* conv2_b  = (const float*)d_in[4];
    const float* gcn1_w   = (const float*)d_in[5];
    const float* gcn1_b   = (const float*)d_in[6];
    const float* gcn2_w   = (const float*)d_in[7];
    const float* gcn2_b   = (const float*)d_in[8];
    const float* gcn3_w   = (const float*)d_in[9];
    const float* gcn3_b   = (const float*)d_in[10];
    const float* policy_w = (const float*)d_in[11];
    const float* policy_b = (const float*)d_in[12];
    float* out = (float*)d_out;

    float *fa;
    uint32_t *xwA, *xwB, *wg2, *wg3;
    cudaGetSymbolAddress((void**)&fa, g_fa);
    cudaGetSymbolAddress((void**)&xwA, g_xwTA);
    cudaGetSymbolAddress((void**)&xwB, g_xwTB);
    cudaGetSymbolAddress((void**)&wg2, g_wg2);
    cudaGetSymbolAddress((void**)&wg3, g_wg3);

    prep_kernel<<<32, 256>>>(conv1_w, conv2_w, gcn1_w, gcn2_w, gcn3_w);
    conv_fused_kernel<<<dim3(5, 19, BB), 256>>>(obs, conv1_b, conv2_b);
    xwdeg_kernel<<<147 + BB*NN, 128>>>();

    gcn_kernel<64,  false><<<dim3(10, BB), 128>>>(xwA, gcn1_b, wg2, xwB, nullptr);
    gcn_kernel<128, false><<<dim3(10, BB), 128>>>(xwB, gcn2_b, wg3, xwA, nullptr);
    gcn_kernel<128, true ><<<dim3(10, BB), 128>>>(xwA, gcn3_b, nullptr, nullptr, fa);

    head_kernel<<<BB, 128>>>(fa, policy_w, policy_b, out);
}